// round 1
// baseline (speedup 1.0000x reference)
#include <cuda_runtime.h>
#include <cuda_bf16.h>
#include <math.h>

// Problem dims
#define BB 32
#define NN 577
#define CC 768
#define HH 3072
#define MROWS (BB*NN)            // 18464
#define ATTN_PER_B (NN*NN)       // 332929
#define OUT_X_ELEMS ((long long)MROWS*CC)   // 14,180,352
#define OUT_ATTN_ELEMS (BB*(NN-1))          // 18,432

// ---------------- scratch (static device globals; no allocations) ----------
__device__ float g_h  [MROWS*CC];        // LN1 output
__device__ float g_qkv[(long long)MROWS*3*CC];
__device__ float g_attn[(long long)BB*ATTN_PER_B];
__device__ float g_y  [MROWS*CC];        // attn @ v
__device__ float g_yt [MROWS*CC];        // per-batch transpose of g_y
__device__ float g_x2 [MROWS*CC];        // 2*(proj out + bias)
__device__ float g_m1 [MROWS*CC];        // LN2 output
__device__ float g_f1 [(long long)MROWS*HH];  // gelu(fc1)

// ---------------- LayerNorm ----------------
__global__ void layernorm_kernel(const float* __restrict__ x,
                                 const float* __restrict__ w,
                                 const float* __restrict__ b,
                                 float* __restrict__ out, int C) {
    long long row = blockIdx.x;
    const float* xr = x + row * C;
    float* orow = out + row * C;
    float s = 0.f, ss = 0.f;
    for (int i = threadIdx.x; i < C; i += blockDim.x) {
        float v = xr[i];
        s += v; ss += v * v;
    }
    __shared__ float red0[32], red1[32];
    #pragma unroll
    for (int o = 16; o > 0; o >>= 1) {
        s  += __shfl_xor_sync(0xffffffffu, s, o);
        ss += __shfl_xor_sync(0xffffffffu, ss, o);
    }
    int lane = threadIdx.x & 31, wid = threadIdx.x >> 5;
    if (lane == 0) { red0[wid] = s; red1[wid] = ss; }
    __syncthreads();
    int nw = blockDim.x >> 5;
    if (threadIdx.x < 32) {
        float a = (threadIdx.x < nw) ? red0[threadIdx.x] : 0.f;
        float c = (threadIdx.x < nw) ? red1[threadIdx.x] : 0.f;
        #pragma unroll
        for (int o = 16; o > 0; o >>= 1) {
            a += __shfl_xor_sync(0xffffffffu, a, o);
            c += __shfl_xor_sync(0xffffffffu, c, o);
        }
        if (threadIdx.x == 0) { red0[0] = a; red1[0] = c; }
    }
    __syncthreads();
    float mean = red0[0] / (float)C;
    float var  = red1[0] / (float)C - mean * mean;
    float inv = rsqrtf(var + 1e-5f);
    for (int i = threadIdx.x; i < C; i += blockDim.x)
        orow[i] = (xr[i] - mean) * inv * w[i] + b[i];
}

// ---------------- generic tiled SGEMM ----------------
// Computes, per batch z:
//   NT=true : C[m,n] = sum_k A[m,k] * B[n,k]    (B row-major [N,K], ldb)
//   NT=false: C[m,n] = sum_k A[m,k] * B[k,n]    (B row-major [K,N], ldb)
// epilogue: v = alpha * (acc + bias[n]);  MODE 1: v = gelu_erf(v);
//           MODE 2: v += resid[m,n]
template <int MODE, bool NT>
__global__ void sgemm_kernel(
    const float* __restrict__ A, int lda, long long strideA,
    const float* __restrict__ B, int ldb, long long strideB,
    float* __restrict__ Cmat, int ldc, long long strideC,
    int M, int N, int K,
    const float* __restrict__ bias, float alpha,
    const float* __restrict__ resid, long long strideR)
{
    const int BM = 128, BN = 128, BK = 8;
    __shared__ float As[BK][BM];
    __shared__ float Bs[BK][BN];

    int bz = blockIdx.z;
    A    += (long long)bz * strideA;
    B    += (long long)bz * strideB;
    Cmat += (long long)bz * strideC;

    int m0 = blockIdx.y * BM;
    int n0 = blockIdx.x * BN;
    int tid = threadIdx.x;
    int tx = tid & 15, ty = tid >> 4;

    float acc[8][8];
    #pragma unroll
    for (int i = 0; i < 8; i++)
        #pragma unroll
        for (int j = 0; j < 8; j++) acc[i][j] = 0.f;

    // load indices: 1024 elems / 256 threads = 4 per thread
    int aIdx = tid * 4;
    int a_m = aIdx / BK, a_k = aIdx % BK;   // A tile [BM][BK] m-major
    int bt_n = aIdx / BK, bt_k = aIdx % BK; // NT B tile [BN][BK] n-major
    int bn_k = aIdx / BN, bn_n = aIdx % BN; // NN B tile [BK][BN] k-major

    for (int k0 = 0; k0 < K; k0 += BK) {
        #pragma unroll
        for (int u = 0; u < 4; u++) {
            int m = m0 + a_m;
            int k = k0 + a_k + u;
            float v = 0.f;
            if (m < M && k < K) v = A[(long long)m * lda + k];
            As[a_k + u][a_m] = v;
        }
        if (NT) {
            #pragma unroll
            for (int u = 0; u < 4; u++) {
                int n = n0 + bt_n;
                int k = k0 + bt_k + u;
                float v = 0.f;
                if (n < N && k < K) v = B[(long long)n * ldb + k];
                Bs[bt_k + u][bt_n] = v;
            }
        } else {
            #pragma unroll
            for (int u = 0; u < 4; u++) {
                int n = n0 + bn_n + u;
                int k = k0 + bn_k;
                float v = 0.f;
                if (n < N && k < K) v = B[(long long)k * ldb + n];
                Bs[bn_k][bn_n + u] = v;
            }
        }
        __syncthreads();
        #pragma unroll
        for (int kk = 0; kk < BK; kk++) {
            float ar[8], br[8];
            #pragma unroll
            for (int i = 0; i < 8; i++) ar[i] = As[kk][ty * 8 + i];
            #pragma unroll
            for (int j = 0; j < 8; j++) br[j] = Bs[kk][tx * 8 + j];
            #pragma unroll
            for (int i = 0; i < 8; i++)
                #pragma unroll
                for (int j = 0; j < 8; j++)
                    acc[i][j] = fmaf(ar[i], br[j], acc[i][j]);
        }
        __syncthreads();
    }

    #pragma unroll
    for (int i = 0; i < 8; i++) {
        int m = m0 + ty * 8 + i;
        if (m >= M) continue;
        #pragma unroll
        for (int j = 0; j < 8; j++) {
            int n = n0 + tx * 8 + j;
            if (n >= N) continue;
            float v = acc[i][j];
            if (bias) v += bias[n];
            v *= alpha;
            if (MODE == 1) {
                // exact GELU: 0.5*x*(1+erf(x/sqrt(2)))
                v = 0.5f * v * (1.0f + erff(v * 0.70710678118654752440f));
            }
            if (MODE == 2) {
                v += resid[(long long)bz * strideR + (long long)m * ldc + n];
            }
            Cmat[(long long)m * ldc + n] = v;
        }
    }
}

// ---------------- softmax over rows (in-place) ----------------
__global__ void softmax_kernel(float* __restrict__ attn, int N) {
    long long row = blockIdx.x;
    float* r = attn + row * (long long)N;
    __shared__ float red[32];
    int lane = threadIdx.x & 31, wid = threadIdx.x >> 5;
    int nw = blockDim.x >> 5;

    float mx = -1e30f;
    for (int i = threadIdx.x; i < N; i += blockDim.x) mx = fmaxf(mx, r[i]);
    #pragma unroll
    for (int o = 16; o > 0; o >>= 1) mx = fmaxf(mx, __shfl_xor_sync(0xffffffffu, mx, o));
    if (lane == 0) red[wid] = mx;
    __syncthreads();
    if (threadIdx.x < 32) {
        float v = (threadIdx.x < nw) ? red[threadIdx.x] : -1e30f;
        #pragma unroll
        for (int o = 16; o > 0; o >>= 1) v = fmaxf(v, __shfl_xor_sync(0xffffffffu, v, o));
        if (threadIdx.x == 0) red[0] = v;
    }
    __syncthreads();
    mx = red[0];
    __syncthreads();

    float s = 0.f;
    for (int i = threadIdx.x; i < N; i += blockDim.x) {
        float e = expf(r[i] - mx);
        r[i] = e;
        s += e;
    }
    #pragma unroll
    for (int o = 16; o > 0; o >>= 1) s += __shfl_xor_sync(0xffffffffu, s, o);
    if (lane == 0) red[wid] = s;
    __syncthreads();
    if (threadIdx.x < 32) {
        float v = (threadIdx.x < nw) ? red[threadIdx.x] : 0.f;
        #pragma unroll
        for (int o = 16; o > 0; o >>= 1) v += __shfl_xor_sync(0xffffffffu, v, o);
        if (threadIdx.x == 0) red[0] = v;
    }
    __syncthreads();
    float inv = 1.0f / red[0];
    for (int i = threadIdx.x; i < N; i += blockDim.x) r[i] *= inv;
}

// ---------------- per-batch transpose: [R][Cc] -> [Cc][R] ----------------
__global__ void transpose_kernel(const float* __restrict__ in, float* __restrict__ out,
                                 int R, int Cc) {
    __shared__ float tile[32][33];
    long long boff = (long long)blockIdx.z * R * Cc;
    const float* ib = in + boff;
    float* ob = out + boff;
    int c0 = blockIdx.x * 32, r0 = blockIdx.y * 32;
    int tx = threadIdx.x, ty = threadIdx.y;
    #pragma unroll
    for (int dy = 0; dy < 32; dy += 8) {
        int r = r0 + ty + dy, c = c0 + tx;
        if (r < R && c < Cc) tile[ty + dy][tx] = ib[(long long)r * Cc + c];
    }
    __syncthreads();
    #pragma unroll
    for (int dy = 0; dy < 32; dy += 8) {
        int c = c0 + ty + dy, r = r0 + tx;
        if (c < Cc && r < R) ob[(long long)c * R + r] = tile[tx][ty + dy];
    }
}

// ---------------- token attention slice ----------------
__global__ void token_attn_kernel(const float* __restrict__ attn, float* __restrict__ out) {
    int idx = blockIdx.x * blockDim.x + threadIdx.x;
    if (idx >= OUT_ATTN_ELEMS) return;
    int b = idx / (NN - 1);
    int j = idx % (NN - 1);
    out[idx] = attn[(long long)b * ATTN_PER_B + 1 + j];
}

// ---------------- launch ----------------
extern "C" void kernel_launch(void* const* d_in, const int* in_sizes, int n_in,
                              void* d_out, int out_size) {
    const float* x       = (const float*)d_in[0];
    const float* norm1_w = (const float*)d_in[1];
    const float* norm1_b = (const float*)d_in[2];
    const float* qkv_w   = (const float*)d_in[3];
    const float* proj_w  = (const float*)d_in[4];
    const float* proj_b  = (const float*)d_in[5];
    const float* norm2_w = (const float*)d_in[6];
    const float* norm2_b = (const float*)d_in[7];
    const float* fc1_w   = (const float*)d_in[8];
    const float* fc1_b   = (const float*)d_in[9];
    const float* fc2_w   = (const float*)d_in[10];
    const float* fc2_b   = (const float*)d_in[11];

    float* out_x    = (float*)d_out;
    float* out_attn = out_x + OUT_X_ELEMS;

    float* h   = nullptr; cudaGetSymbolAddress((void**)&h,   g_h);
    float* qkv = nullptr; cudaGetSymbolAddress((void**)&qkv, g_qkv);
    float* attn= nullptr; cudaGetSymbolAddress((void**)&attn,g_attn);
    float* y   = nullptr; cudaGetSymbolAddress((void**)&y,   g_y);
    float* yt  = nullptr; cudaGetSymbolAddress((void**)&yt,  g_yt);
    float* x2  = nullptr; cudaGetSymbolAddress((void**)&x2,  g_x2);
    float* m1  = nullptr; cudaGetSymbolAddress((void**)&m1,  g_m1);
    float* f1  = nullptr; cudaGetSymbolAddress((void**)&f1,  g_f1);

    const float scale = 0.03608439182435161f; // 768^-0.5

    // 1) LN1
    layernorm_kernel<<<MROWS, 256>>>(x, norm1_w, norm1_b, h, CC);

    // 2) qkv = h @ qkv_w^T   [18464 x 2304]
    sgemm_kernel<0, true><<<dim3((3 * CC) / 128, (MROWS + 127) / 128, 1), 256>>>(
        h, CC, 0, qkv_w, CC, 0, qkv, 3 * CC, 0,
        MROWS, 3 * CC, CC, nullptr, 1.0f, nullptr, 0);

    // 3) S = scale * q @ k^T per batch  [577 x 577] x 32
    sgemm_kernel<0, true><<<dim3((NN + 127) / 128, (NN + 127) / 128, BB), 256>>>(
        qkv,        3 * CC, (long long)NN * 3 * CC,
        qkv + CC,   3 * CC, (long long)NN * 3 * CC,
        attn, NN, (long long)ATTN_PER_B,
        NN, NN, CC, nullptr, scale, nullptr, 0);

    // 4) softmax rows
    softmax_kernel<<<BB * NN, 256>>>(attn, NN);

    // 5) y = attn @ v per batch  [577 x 768]
    sgemm_kernel<0, false><<<dim3((CC + 127) / 128, (NN + 127) / 128, BB), 256>>>(
        attn, NN, (long long)ATTN_PER_B,
        qkv + 2 * CC, 3 * CC, (long long)NN * 3 * CC,
        y, CC, (long long)NN * CC,
        NN, CC, NN, nullptr, 1.0f, nullptr, 0);

    // 6) y^T per batch (the transpose+reshape in the reference)
    transpose_kernel<<<dim3((CC + 31) / 32, (NN + 31) / 32, BB), dim3(32, 8)>>>(
        y, yt, NN, CC);

    // 7) x2 = 2*(yt_flat @ proj_w^T + proj_b)
    sgemm_kernel<0, true><<<dim3(CC / 128, (MROWS + 127) / 128, 1), 256>>>(
        yt, CC, 0, proj_w, CC, 0, x2, CC, 0,
        MROWS, CC, CC, proj_b, 2.0f, nullptr, 0);

    // 8) LN2
    layernorm_kernel<<<MROWS, 256>>>(x2, norm2_w, norm2_b, m1, CC);

    // 9) f1 = gelu(m1 @ fc1_w^T + fc1_b)   [18464 x 3072]
    sgemm_kernel<1, true><<<dim3(HH / 128, (MROWS + 127) / 128, 1), 256>>>(
        m1, CC, 0, fc1_w, CC, 0, f1, HH, 0,
        MROWS, HH, CC, fc1_b, 1.0f, nullptr, 0);

    // 10) out_x = x2 + f1 @ fc2_w^T + fc2_b
    sgemm_kernel<2, true><<<dim3(CC / 128, (MROWS + 127) / 128, 1), 256>>>(
        f1, HH, 0, fc2_w, HH, 0, out_x, CC, 0,
        MROWS, CC, HH, fc2_b, 1.0f, x2, 0);

    // 11) token_attn = attn[:, 0, 1:]
    token_attn_kernel<<<(OUT_ATTN_ELEMS + 255) / 256, 256>>>(attn, out_attn);
}

// round 3
// speedup vs baseline: 3.8567x; 3.8567x over previous
#include <cuda_runtime.h>
#include <cuda_bf16.h>
#include <math.h>
#include <stdint.h>

// Problem dims
#define BB 32
#define NN 577
#define CC 768
#define HH 3072
#define MROWS (BB*NN)            // 18464
#define NPAD 608                 // 577 padded to multiple of 32 (K-chunk)
#define OUT_X_ELEMS ((long long)MROWS*CC)
#define OUT_ATTN_ELEMS (BB*(NN-1))

// ---------------- helpers ----------------
__device__ __forceinline__ uint32_t smem_u32(const void* p) {
    uint32_t a;
    asm("{ .reg .u64 t; cvta.to.shared.u64 t, %1; cvt.u32.u64 %0, t; }" : "=r"(a) : "l"(p));
    return a;
}

#define LDSM_X4(r, a) \
    asm volatile("ldmatrix.sync.aligned.m8n8.x4.shared.b16 {%0,%1,%2,%3}, [%4];" \
        : "=r"((r)[0]),"=r"((r)[1]),"=r"((r)[2]),"=r"((r)[3]) : "r"(a))

__device__ __forceinline__ void mma16816(float* c, const uint32_t* a, const uint32_t* b) {
    asm volatile("mma.sync.aligned.m16n8k16.row.col.f32.bf16.bf16.f32 "
        "{%0,%1,%2,%3}, {%4,%5,%6,%7}, {%8,%9}, {%0,%1,%2,%3};"
        : "+f"(c[0]),"+f"(c[1]),"+f"(c[2]),"+f"(c[3])
        : "r"(a[0]),"r"(a[1]),"r"(a[2]),"r"(a[3]),"r"(b[0]),"r"(b[1]));
}

__device__ __forceinline__ void cp_async16(uint32_t dst, const void* src, int srcsz) {
    asm volatile("cp.async.cg.shared.global [%0], [%1], 16, %2;"
        :: "r"(dst), "l"(src), "r"(srcsz));
}
#define CP_COMMIT() asm volatile("cp.async.commit_group;")
#define CP_WAIT0()  asm volatile("cp.async.wait_group 0;")
#define CP_WAIT1()  asm volatile("cp.async.wait_group 1;")

// smem tile: 128 rows x 64B (32 bf16). XOR swizzle on 16B chunks so each
// 8-row LDSM phase hits distinct bank groups.
__device__ __forceinline__ uint32_t swz_off(int row, int kc) {
    int c = kc ^ (row & 3) ^ ((row >> 2) & 1);
    return (uint32_t)(row * 64 + c * 16);
}

__device__ __forceinline__ void split_f(float v, __nv_bfloat16& h, __nv_bfloat16& l) {
    h = __float2bfloat16(v);
    l = __float2bfloat16(v - __bfloat162float(h));
}

// ---------------- scratch (device globals; no allocations) ----------------
__device__ __nv_bfloat16 g_h_hi[(size_t)MROWS*CC],   g_h_lo[(size_t)MROWS*CC];
__device__ __nv_bfloat16 g_wqkv_hi[(size_t)3*CC*CC], g_wqkv_lo[(size_t)3*CC*CC];
__device__ __nv_bfloat16 g_wproj_hi[(size_t)CC*CC],  g_wproj_lo[(size_t)CC*CC];
__device__ __nv_bfloat16 g_wfc1_hi[(size_t)HH*CC],   g_wfc1_lo[(size_t)HH*CC];
__device__ __nv_bfloat16 g_wfc2_hi[(size_t)CC*HH],   g_wfc2_lo[(size_t)CC*HH];
__device__ __nv_bfloat16 g_qkv_hi[(size_t)MROWS*3*CC], g_qkv_lo[(size_t)MROWS*3*CC];
__device__ float         g_attn[(size_t)BB*NN*NN];
__device__ __nv_bfloat16 g_attn_hi[(size_t)BB*NN*NPAD], g_attn_lo[(size_t)BB*NN*NPAD];
__device__ __nv_bfloat16 g_vT_hi[(size_t)BB*CC*NPAD],   g_vT_lo[(size_t)BB*CC*NPAD];
__device__ float         g_y[(size_t)MROWS*CC];
__device__ __nv_bfloat16 g_yt_hi[(size_t)MROWS*CC],  g_yt_lo[(size_t)MROWS*CC];
__device__ float         g_x2[(size_t)MROWS*CC];
__device__ __nv_bfloat16 g_m1_hi[(size_t)MROWS*CC],  g_m1_lo[(size_t)MROWS*CC];
__device__ __nv_bfloat16 g_f1_hi[(size_t)MROWS*HH],  g_f1_lo[(size_t)MROWS*HH];

// ============= mma.sync bf16x3 GEMM =============
// C[m,n] = sum_k (Ah+Al)[m,k]*(Bh+Bl)[n,k]  (both K-contiguous, NT)
// epilogue: v = alpha*(acc + bias[n]); optional exact GELU; optional +resid
// Tile 128x128xK32, 8 warps (warp tile 64x32), 2-stage cp.async pipeline.
#define STAGE_BYTES 32768   // 4 matrices x 128 rows x 64B
#define SMEM_BYTES  (2*STAGE_BYTES)

template<bool GELU, bool RESID, bool WF32, bool WSPLIT>
__global__ void __launch_bounds__(256, 2) mma_gemm(
    const __nv_bfloat16* __restrict__ Ah, const __nv_bfloat16* __restrict__ Al,
    int lda, long long sA,
    const __nv_bfloat16* __restrict__ Bh, const __nv_bfloat16* __restrict__ Bl,
    int ldb, long long sB,
    float* __restrict__ Cf, __nv_bfloat16* __restrict__ Ch, __nv_bfloat16* __restrict__ Cl,
    int ldc, long long sC,
    int M, int N, int K,
    const float* __restrict__ bias, float alpha,
    const float* __restrict__ resid, long long sR)
{
    extern __shared__ char smem[];
    const uint32_t sbase = smem_u32(smem);
    const int tid = threadIdx.x;
    const int wid = tid >> 5, lane = tid & 31;
    const int bz = blockIdx.z;
    const long long m0 = (long long)blockIdx.y * 128;
    const long long n0 = (long long)blockIdx.x * 128;
    const int warp_m = (wid & 1) * 64;
    const int warp_n = (wid >> 1) * 32;

    Ah += bz * sA; Al += bz * sA;
    Bh += bz * sB; Bl += bz * sB;

    const int nCh = K >> 5;   // K is always a multiple of 32

    float acc[4][4][4];
    #pragma unroll
    for (int i = 0; i < 4; i++)
        #pragma unroll
        for (int j = 0; j < 4; j++)
            #pragma unroll
            for (int e = 0; e < 4; e++) acc[i][j][e] = 0.f;

    // ---- stage loader ----
    auto load_stage = [&](int it) {
        const uint32_t sb = sbase + (uint32_t)(it & 1) * STAGE_BYTES;
        const long long k0 = (long long)it << 5;
        #pragma unroll
        for (int u = 0; u < 8; u++) {
            int idx = u * 256 + tid;
            int mat = idx >> 9;        // 0:Ah 1:Al 2:Bh 3:Bl
            int rem = idx & 511;
            int row = rem >> 2;
            int kc  = rem & 3;
            const __nv_bfloat16* src = (mat == 0) ? Ah : (mat == 1) ? Al
                                      : (mat == 2) ? Bh : Bl;
            long long r0 = (mat < 2) ? m0 : n0;
            int rt = (mat < 2) ? M : N;
            int ld = (mat < 2) ? lda : ldb;
            long long gr = r0 + row;
            int ok = (gr < rt) ? 16 : 0;
            const __nv_bfloat16* gp = src + (ok ? gr * (long long)ld : 0) + k0 + kc * 8;
            cp_async16(sb + (uint32_t)mat * 8192 + swz_off(row, kc), gp, ok);
        }
        CP_COMMIT();
    };

    // ---- stage compute ----
    auto compute_stage = [&](int it) {
        const uint32_t sb = sbase + (uint32_t)(it & 1) * STAGE_BYTES;
        #pragma unroll
        for (int ks = 0; ks < 2; ks++) {
            const int kc0 = ks * 2;
            uint32_t ah[4][4], al[4][4], bh[4][2], bl[4][2];
            // A frags: addressed rows = m, lanes 0-15 rows, lanes>=16 k+8
            const int arow = lane & 15;
            const int akc  = kc0 + (lane >> 4);
            #pragma unroll
            for (int i = 0; i < 4; i++) {
                uint32_t off = swz_off(warp_m + i * 16 + arow, akc);
                LDSM_X4(ah[i], sb + off);
                LDSM_X4(al[i], sb + 8192 + off);
            }
            // B frags: addressed rows = n
            const int brow = ((lane >> 4) << 3) + (lane & 7);
            const int bkc  = kc0 + ((lane >> 3) & 1);
            #pragma unroll
            for (int j = 0; j < 2; j++) {
                uint32_t r[4];
                uint32_t off = swz_off(warp_n + j * 16 + brow, bkc);
                LDSM_X4(r, sb + 16384 + off);
                bh[2*j][0] = r[0]; bh[2*j][1] = r[1];
                bh[2*j+1][0] = r[2]; bh[2*j+1][1] = r[3];
                LDSM_X4(r, sb + 24576 + off);
                bl[2*j][0] = r[0]; bl[2*j][1] = r[1];
                bl[2*j+1][0] = r[2]; bl[2*j+1][1] = r[3];
            }
            #pragma unroll
            for (int i = 0; i < 4; i++)
                #pragma unroll
                for (int j = 0; j < 4; j++) {
                    mma16816(acc[i][j], ah[i], bh[j]);
                    mma16816(acc[i][j], ah[i], bl[j]);
                    mma16816(acc[i][j], al[i], bh[j]);
                }
        }
    };

    // ---- pipeline ----
    load_stage(0);
    for (int it = 0; it < nCh; it++) {
        if (it + 1 < nCh) { load_stage(it + 1); CP_WAIT1(); }
        else              { CP_WAIT0(); }
        __syncthreads();
        compute_stage(it);
        __syncthreads();
    }

    // ---- epilogue ----
    const int tm = lane >> 2;
    const int tn = (lane & 3) * 2;
    #pragma unroll
    for (int i = 0; i < 4; i++) {
        #pragma unroll
        for (int half = 0; half < 2; half++) {
            long long m = m0 + warp_m + i * 16 + tm + half * 8;
            if (m >= M) continue;
            #pragma unroll
            for (int j = 0; j < 4; j++) {
                #pragma unroll
                for (int e = 0; e < 2; e++) {
                    long long n = n0 + warp_n + j * 8 + tn + e;
                    if (n >= N) continue;
                    float v = acc[i][j][half * 2 + e];
                    if (bias) v += bias[n];
                    v *= alpha;
                    if (GELU) v = 0.5f * v * (1.0f + erff(v * 0.70710678118654752440f));
                    if (RESID) v += resid[bz * sR + m * (long long)ldc + n];
                    long long o = (long long)bz * sC + m * (long long)ldc + n;
                    if (WF32) Cf[o] = v;
                    if (WSPLIT) { __nv_bfloat16 h, l; split_f(v, h, l); Ch[o] = h; Cl[o] = l; }
                }
            }
        }
    }
}

// ---------------- LayerNorm -> bf16 hi/lo ----------------
__global__ void ln_split_kernel(const float* __restrict__ x,
                                const float* __restrict__ w,
                                const float* __restrict__ b,
                                __nv_bfloat16* __restrict__ oh,
                                __nv_bfloat16* __restrict__ ol) {
    long long row = blockIdx.x;
    const float* xr = x + row * CC;
    float s = 0.f, ss = 0.f;
    for (int i = threadIdx.x; i < CC; i += blockDim.x) {
        float v = xr[i]; s += v; ss += v * v;
    }
    __shared__ float r0[32], r1[32];
    #pragma unroll
    for (int o = 16; o > 0; o >>= 1) {
        s  += __shfl_xor_sync(0xffffffffu, s, o);
        ss += __shfl_xor_sync(0xffffffffu, ss, o);
    }
    int lane = threadIdx.x & 31, wd = threadIdx.x >> 5;
    if (lane == 0) { r0[wd] = s; r1[wd] = ss; }
    __syncthreads();
    int nw = blockDim.x >> 5;
    if (threadIdx.x < 32) {
        float a = (threadIdx.x < nw) ? r0[threadIdx.x] : 0.f;
        float c = (threadIdx.x < nw) ? r1[threadIdx.x] : 0.f;
        #pragma unroll
        for (int o = 16; o > 0; o >>= 1) {
            a += __shfl_xor_sync(0xffffffffu, a, o);
            c += __shfl_xor_sync(0xffffffffu, c, o);
        }
        if (threadIdx.x == 0) { r0[0] = a; r1[0] = c; }
    }
    __syncthreads();
    float mean = r0[0] / (float)CC;
    float inv = rsqrtf(r1[0] / (float)CC - mean * mean + 1e-5f);
    for (int i = threadIdx.x; i < CC; i += blockDim.x) {
        float v = (xr[i] - mean) * inv * w[i] + b[i];
        __nv_bfloat16 h, l; split_f(v, h, l);
        oh[row * CC + i] = h; ol[row * CC + i] = l;
    }
}

// ---------------- softmax (f32 in-place) + hi/lo padded to NPAD ----------------
__global__ void softmax_split_kernel(float* __restrict__ attn,
                                     __nv_bfloat16* __restrict__ oh,
                                     __nv_bfloat16* __restrict__ ol) {
    long long row = blockIdx.x;
    float* r = attn + row * NN;
    __shared__ float red[32];
    int lane = threadIdx.x & 31, wd = threadIdx.x >> 5;
    int nw = blockDim.x >> 5;

    float mx = -1e30f;
    for (int i = threadIdx.x; i < NN; i += blockDim.x) mx = fmaxf(mx, r[i]);
    #pragma unroll
    for (int o = 16; o > 0; o >>= 1) mx = fmaxf(mx, __shfl_xor_sync(0xffffffffu, mx, o));
    if (lane == 0) red[wd] = mx;
    __syncthreads();
    if (threadIdx.x < 32) {
        float v = (threadIdx.x < nw) ? red[threadIdx.x] : -1e30f;
        #pragma unroll
        for (int o = 16; o > 0; o >>= 1) v = fmaxf(v, __shfl_xor_sync(0xffffffffu, v, o));
        if (threadIdx.x == 0) red[0] = v;
    }
    __syncthreads();
    mx = red[0];
    __syncthreads();

    float s = 0.f;
    for (int i = threadIdx.x; i < NN; i += blockDim.x) {
        float e = expf(r[i] - mx); r[i] = e; s += e;
    }
    #pragma unroll
    for (int o = 16; o > 0; o >>= 1) s += __shfl_xor_sync(0xffffffffu, s, o);
    if (lane == 0) red[wd] = s;
    __syncthreads();
    if (threadIdx.x < 32) {
        float v = (threadIdx.x < nw) ? red[threadIdx.x] : 0.f;
        #pragma unroll
        for (int o = 16; o > 0; o >>= 1) v += __shfl_xor_sync(0xffffffffu, v, o);
        if (threadIdx.x == 0) red[0] = v;
    }
    __syncthreads();
    float inv = 1.0f / red[0];
    for (int i = threadIdx.x; i < NPAD; i += blockDim.x) {
        if (i < NN) {
            float v = r[i] * inv;
            r[i] = v;
            __nv_bfloat16 h, l; split_f(v, h, l);
            oh[row * NPAD + i] = h; ol[row * NPAD + i] = l;
        } else {
            oh[row * NPAD + i] = __float2bfloat16(0.f);
            ol[row * NPAD + i] = __float2bfloat16(0.f);
        }
    }
}

// ---------------- transpose (bf16 hi+lo in) -> hi/lo out, zero-padded rows ----
__global__ void transpose_pair_kernel(const __nv_bfloat16* __restrict__ ih,
                                      const __nv_bfloat16* __restrict__ il,
                                      int ld_in, long long sIn,
                                      __nv_bfloat16* __restrict__ oh,
                                      __nv_bfloat16* __restrict__ ol,
                                      int ld_out, long long sOut,
                                      int R, int Rpad, int Cc) {
    __shared__ float tile[32][33];
    long long bi = (long long)blockIdx.z * sIn;
    long long bo = (long long)blockIdx.z * sOut;
    int c0 = blockIdx.x * 32, r0 = blockIdx.y * 32;
    int tx = threadIdx.x, ty = threadIdx.y;
    #pragma unroll
    for (int dy = 0; dy < 32; dy += 8) {
        int r = r0 + ty + dy, c = c0 + tx;
        float v = 0.f;
        if (r < R && c < Cc) {
            long long o = bi + (long long)r * ld_in + c;
            v = __bfloat162float(ih[o]) + __bfloat162float(il[o]);
        }
        tile[ty + dy][tx] = v;
    }
    __syncthreads();
    #pragma unroll
    for (int dy = 0; dy < 32; dy += 8) {
        int c = c0 + ty + dy, r = r0 + tx;
        if (c < Cc && r < Rpad) {
            __nv_bfloat16 h, l; split_f(tile[tx][ty + dy], h, l);
            long long o = bo + (long long)c * ld_out + r;
            oh[o] = h; ol[o] = l;
        }
    }
}

// ---------------- transpose (f32 in) -> hi/lo out ----------------
__global__ void transpose_f32split_kernel(const float* __restrict__ in,
                                          int ld_in, long long sIn,
                                          __nv_bfloat16* __restrict__ oh,
                                          __nv_bfloat16* __restrict__ ol,
                                          int ld_out, long long sOut, int R, int Cc) {
    __shared__ float tile[32][33];
    long long bi = (long long)blockIdx.z * sIn;
    long long bo = (long long)blockIdx.z * sOut;
    int c0 = blockIdx.x * 32, r0 = blockIdx.y * 32;
    int tx = threadIdx.x, ty = threadIdx.y;
    #pragma unroll
    for (int dy = 0; dy < 32; dy += 8) {
        int r = r0 + ty + dy, c = c0 + tx;
        if (r < R && c < Cc) tile[ty + dy][tx] = in[bi + (long long)r * ld_in + c];
    }
    __syncthreads();
    #pragma unroll
    for (int dy = 0; dy < 32; dy += 8) {
        int c = c0 + ty + dy, r = r0 + tx;
        if (c < Cc && r < R) {
            __nv_bfloat16 h, l; split_f(tile[tx][ty + dy], h, l);
            long long o = bo + (long long)c * ld_out + r;
            oh[o] = h; ol[o] = l;
        }
    }
}

// ---------------- weight split ----------------
__global__ void split_kernel(const float* __restrict__ in,
                             __nv_bfloat16* __restrict__ oh,
                             __nv_bfloat16* __restrict__ ol, long long n) {
    long long i = (long long)blockIdx.x * blockDim.x + threadIdx.x;
    if (i < n) { __nv_bfloat16 h, l; split_f(in[i], h, l); oh[i] = h; ol[i] = l; }
}

// ---------------- token attention slice ----------------
__global__ void token_attn_kernel(const float* __restrict__ attn, float* __restrict__ out) {
    int idx = blockIdx.x * blockDim.x + threadIdx.x;
    if (idx >= OUT_ATTN_ELEMS) return;
    int b = idx / (NN - 1);
    int j = idx % (NN - 1);
    out[idx] = attn[(long long)b * NN * NN + 1 + j];
}

// ---------------- launch ----------------
extern "C" void kernel_launch(void* const* d_in, const int* in_sizes, int n_in,
                              void* d_out, int out_size) {
    const float* x       = (const float*)d_in[0];
    const float* norm1_w = (const float*)d_in[1];
    const float* norm1_b = (const float*)d_in[2];
    const float* qkv_w   = (const float*)d_in[3];
    const float* proj_w  = (const float*)d_in[4];
    const float* proj_b  = (const float*)d_in[5];
    const float* norm2_w = (const float*)d_in[6];
    const float* norm2_b = (const float*)d_in[7];
    const float* fc1_w   = (const float*)d_in[8];
    const float* fc1_b   = (const float*)d_in[9];
    const float* fc2_w   = (const float*)d_in[10];
    const float* fc2_b   = (const float*)d_in[11];

    float* out_x    = (float*)d_out;
    float* out_attn = out_x + OUT_X_ELEMS;

    __nv_bfloat16 *h_hi, *h_lo, *wqkv_hi, *wqkv_lo, *wproj_hi, *wproj_lo;
    __nv_bfloat16 *wfc1_hi, *wfc1_lo, *wfc2_hi, *wfc2_lo;
    __nv_bfloat16 *qkv_hi, *qkv_lo, *attn_hi, *attn_lo, *vT_hi, *vT_lo;
    __nv_bfloat16 *yt_hi, *yt_lo, *m1_hi, *m1_lo, *f1_hi, *f1_lo;
    float *attn, *y, *x2;
    cudaGetSymbolAddress((void**)&h_hi, g_h_hi);   cudaGetSymbolAddress((void**)&h_lo, g_h_lo);
    cudaGetSymbolAddress((void**)&wqkv_hi, g_wqkv_hi); cudaGetSymbolAddress((void**)&wqkv_lo, g_wqkv_lo);
    cudaGetSymbolAddress((void**)&wproj_hi, g_wproj_hi); cudaGetSymbolAddress((void**)&wproj_lo, g_wproj_lo);
    cudaGetSymbolAddress((void**)&wfc1_hi, g_wfc1_hi); cudaGetSymbolAddress((void**)&wfc1_lo, g_wfc1_lo);
    cudaGetSymbolAddress((void**)&wfc2_hi, g_wfc2_hi); cudaGetSymbolAddress((void**)&wfc2_lo, g_wfc2_lo);
    cudaGetSymbolAddress((void**)&qkv_hi, g_qkv_hi); cudaGetSymbolAddress((void**)&qkv_lo, g_qkv_lo);
    cudaGetSymbolAddress((void**)&attn, g_attn);
    cudaGetSymbolAddress((void**)&attn_hi, g_attn_hi); cudaGetSymbolAddress((void**)&attn_lo, g_attn_lo);
    cudaGetSymbolAddress((void**)&vT_hi, g_vT_hi); cudaGetSymbolAddress((void**)&vT_lo, g_vT_lo);
    cudaGetSymbolAddress((void**)&y, g_y);
    cudaGetSymbolAddress((void**)&yt_hi, g_yt_hi); cudaGetSymbolAddress((void**)&yt_lo, g_yt_lo);
    cudaGetSymbolAddress((void**)&x2, g_x2);
    cudaGetSymbolAddress((void**)&m1_hi, g_m1_hi); cudaGetSymbolAddress((void**)&m1_lo, g_m1_lo);
    cudaGetSymbolAddress((void**)&f1_hi, g_f1_hi); cudaGetSymbolAddress((void**)&f1_lo, g_f1_lo);

    cudaFuncSetAttribute(mma_gemm<false,false,false,true>,  cudaFuncAttributeMaxDynamicSharedMemorySize, SMEM_BYTES);
    cudaFuncSetAttribute(mma_gemm<false,false,true,false>,  cudaFuncAttributeMaxDynamicSharedMemorySize, SMEM_BYTES);
    cudaFuncSetAttribute(mma_gemm<true,false,false,true>,   cudaFuncAttributeMaxDynamicSharedMemorySize, SMEM_BYTES);
    cudaFuncSetAttribute(mma_gemm<false,true,true,false>,   cudaFuncAttributeMaxDynamicSharedMemorySize, SMEM_BYTES);

    const float scale = 0.03608439182435161f; // 768^-0.5

    // 0) split weights to bf16 hi/lo
    split_kernel<<<(3*CC*CC + 255)/256, 256>>>(qkv_w, wqkv_hi, wqkv_lo, (long long)3*CC*CC);
    split_kernel<<<(CC*CC + 255)/256, 256>>>(proj_w, wproj_hi, wproj_lo, (long long)CC*CC);
    split_kernel<<<((long long)HH*CC + 255)/256, 256>>>(fc1_w, wfc1_hi, wfc1_lo, (long long)HH*CC);
    split_kernel<<<((long long)CC*HH + 255)/256, 256>>>(fc2_w, wfc2_hi, wfc2_lo, (long long)CC*HH);

    // 1) LN1 -> h hi/lo
    ln_split_kernel<<<MROWS, 256>>>(x, norm1_w, norm1_b, h_hi, h_lo);

    // 2) qkv = h @ qkv_w^T  -> hi/lo
    mma_gemm<false,false,false,true><<<dim3(18, 145, 1), 256, SMEM_BYTES>>>(
        h_hi, h_lo, CC, 0, wqkv_hi, wqkv_lo, CC, 0,
        nullptr, qkv_hi, qkv_lo, 3*CC, 0,
        MROWS, 3*CC, CC, nullptr, 1.f, nullptr, 0);

    // 3) attn = scale * q @ k^T per batch -> f32
    mma_gemm<false,false,true,false><<<dim3(5, 5, BB), 256, SMEM_BYTES>>>(
        qkv_hi, qkv_lo, 3*CC, (long long)NN*3*CC,
        qkv_hi + CC, qkv_lo + CC, 3*CC, (long long)NN*3*CC,
        attn, nullptr, nullptr, NN, (long long)NN*NN,
        NN, NN, CC, nullptr, scale, nullptr, 0);

    // 4) softmax (f32 in place) + hi/lo (row length NPAD, zero-padded)
    softmax_split_kernel<<<MROWS, 256>>>(attn, attn_hi, attn_lo);

    // 5) vT per batch from qkv hi/lo (v = cols [1536,2304)), rows padded to NPAD
    transpose_pair_kernel<<<dim3(24, 19, BB), dim3(32, 8)>>>(
        qkv_hi + 2*CC, qkv_lo + 2*CC, 3*CC, (long long)NN*3*CC,
        vT_hi, vT_lo, NPAD, (long long)CC*NPAD, NN, NPAD, CC);

    // 6) y = attn @ v  (NT with vT) -> f32, K padded to NPAD with zeros
    mma_gemm<false,false,true,false><<<dim3(6, 5, BB), 256, SMEM_BYTES>>>(
        attn_hi, attn_lo, NPAD, (long long)NN*NPAD,
        vT_hi, vT_lo, NPAD, (long long)CC*NPAD,
        y, nullptr, nullptr, CC, (long long)NN*CC,
        NN, CC, NPAD, nullptr, 1.f, nullptr, 0);

    // 7) yt = y^T per batch -> hi/lo (dense [B][768][577])
    transpose_f32split_kernel<<<dim3(24, 19, BB), dim3(32, 8)>>>(
        y, CC, (long long)NN*CC,
        yt_hi, yt_lo, NN, (long long)CC*NN, NN, CC);

    // 8) x2 = 2*(yt @ proj_w^T + proj_b) -> f32
    mma_gemm<false,false,true,false><<<dim3(6, 145, 1), 256, SMEM_BYTES>>>(
        yt_hi, yt_lo, CC, 0, wproj_hi, wproj_lo, CC, 0,
        x2, nullptr, nullptr, CC, 0,
        MROWS, CC, CC, proj_b, 2.f, nullptr, 0);

    // 9) LN2 -> m1 hi/lo
    ln_split_kernel<<<MROWS, 256>>>(x2, norm2_w, norm2_b, m1_hi, m1_lo);

    // 10) f1 = gelu(m1 @ fc1_w^T + fc1_b) -> hi/lo
    mma_gemm<true,false,false,true><<<dim3(24, 145, 1), 256, SMEM_BYTES>>>(
        m1_hi, m1_lo, CC, 0, wfc1_hi, wfc1_lo, CC, 0,
        nullptr, f1_hi, f1_lo, HH, 0,
        MROWS, HH, CC, fc1_b, 1.f, nullptr, 0);

    // 11) out_x = x2 + f1 @ fc2_w^T + fc2_b
    mma_gemm<false,true,true,false><<<dim3(6, 145, 1), 256, SMEM_BYTES>>>(
        f1_hi, f1_lo, HH, 0, wfc2_hi, wfc2_lo, HH, 0,
        out_x, nullptr, nullptr, CC, 0,
        MROWS, CC, HH, fc2_b, 1.f, x2, 0);

    // 12) token_attn
    token_attn_kernel<<<(OUT_ATTN_ELEMS + 255)/256, 256>>>(attn, out_attn);
}